// round 3
// baseline (speedup 1.0000x reference)
#include <cuda_runtime.h>

#define NN 100000
#define EE 600000
#define DD 128

// ---------------- scratch (static __device__, no allocation) ----------------
__device__ float g_h[(size_t)NN * DD];     // x @ W
__device__ float g_acc[(size_t)NN * DD];   // aggregated messages
__device__ float g_dinv[NN];
__device__ int   g_deg[NN];
__device__ float g_colsum[DD];
__device__ float g_colsumsq[DD];
__device__ float g_scale[DD];
__device__ float g_shift[DD];
__device__ int   g_ei32;                   // 1 if edge_index stored as int32

// ---------------- edge index decode (int64 or int32, range-guarded) --------
__device__ __forceinline__ int load_src(const void* ei, int e) {
    return g_ei32 ? ((const int*)ei)[e] : (int)((const long long*)ei)[e];
}
__device__ __forceinline__ int load_dst(const void* ei, int e) {
    return g_ei32 ? ((const int*)ei)[EE + e] : (int)((const long long*)ei)[EE + e];
}

// Detect dtype: if any of the first 4096 int64-decoded entries is out of
// [0, NN), the buffer must be int32. Deterministic (pure function of input).
__global__ void k_detect(const void* ei) {
    if (threadIdx.x == 0 && blockIdx.x == 0) {
        const long long* p = (const long long*)ei;
        int bad = 0;
        for (int i = 0; i < 4096; i++) {
            long long v = p[i];
            if (v < 0 || v >= NN) { bad = 1; break; }
        }
        g_ei32 = bad;
    }
}

// ---------------- kernels ----------------

__global__ void k_zero() {
    int i = blockIdx.x * blockDim.x + threadIdx.x;
    if (i < NN) g_deg[i] = 0;
    if (i < DD) { g_colsum[i] = 0.f; g_colsumsq[i] = 0.f; }
}

__global__ void k_degree(const void* __restrict__ ei) {
    int i = blockIdx.x * blockDim.x + threadIdx.x;
    if (i < EE) {
        int d = load_dst(ei, i);
        if ((unsigned)d < NN) atomicAdd(&g_deg[d], 1);
    }
}

__global__ void k_dinv() {
    int i = blockIdx.x * blockDim.x + threadIdx.x;
    if (i < NN) g_dinv[i] = rsqrtf((float)g_deg[i] + 1.0f);
}

// h = X @ W : block computes 64 rows x 128 cols, four K-chunks of 32.
// Static shared: Ws [32][128], xs k-major [32][68] (padded rows). 25 KB total.
__global__ void k_gemm(const float* __restrict__ X, const float* __restrict__ W) {
    __shared__ float Ws[32 * 128];
    __shared__ float xs[32 * 68];
    const int tid = threadIdx.x;  // 256 threads
    const int tx  = tid & 31;     // col group: cols tx*4..tx*4+3
    const int ty  = tid >> 5;     // row group: rows ty*8..ty*8+7
    const int rowBase = blockIdx.x * 64;

    float acc[8][4];
#pragma unroll
    for (int i = 0; i < 8; i++)
#pragma unroll
        for (int j = 0; j < 4; j++) acc[i][j] = 0.f;

    for (int kc = 0; kc < 4; kc++) {
        __syncthreads();
        const float4* Wg = (const float4*)(W + (size_t)kc * 32 * DD);
        float4* Ws4 = (float4*)Ws;
#pragma unroll
        for (int i = 0; i < 4; i++) Ws4[tid + 256 * i] = Wg[tid + 256 * i];
#pragma unroll
        for (int i = 0; i < 8; i++) {
            int idx = tid + 256 * i;
            int r = idx >> 5;       // 0..63
            int k = idx & 31;       // 0..31 (consecutive lanes -> coalesced)
            int row = rowBase + r;
            xs[k * 68 + r] = (row < NN) ? X[(size_t)row * DD + kc * 32 + k] : 0.f;
        }
        __syncthreads();
#pragma unroll
        for (int k = 0; k < 32; k++) {
            float4 w  = ((const float4*)(Ws + k * DD))[tx];
            float4 xa = *(const float4*)(xs + k * 68 + ty * 8);
            float4 xb = *(const float4*)(xs + k * 68 + ty * 8 + 4);
            float xr[8] = {xa.x, xa.y, xa.z, xa.w, xb.x, xb.y, xb.z, xb.w};
#pragma unroll
            for (int i = 0; i < 8; i++) {
                acc[i][0] += xr[i] * w.x;
                acc[i][1] += xr[i] * w.y;
                acc[i][2] += xr[i] * w.z;
                acc[i][3] += xr[i] * w.w;
            }
        }
    }
#pragma unroll
    for (int i = 0; i < 8; i++) {
        int row = rowBase + ty * 8 + i;
        if (row < NN) {
            float4 v = make_float4(acc[i][0], acc[i][1], acc[i][2], acc[i][3]);
            ((float4*)(g_h + (size_t)row * DD))[tx] = v;
        }
    }
}

// acc[i] = h[i] * dinv[i]^2 + b   (self-loop message + bias)
__global__ void k_init(const float* __restrict__ b) {
    int idx = blockIdx.x * blockDim.x + threadIdx.x;   // one float4 each
    if (idx >= NN * 32) return;
    int node = idx >> 5;
    int c4   = idx & 31;
    float dv = g_dinv[node];
    float nrm = dv * dv;
    float4 h  = ((const float4*)g_h)[idx];
    float4 bb = ((const float4*)b)[c4];
    float4 o  = make_float4(h.x * nrm + bb.x, h.y * nrm + bb.y,
                            h.z * nrm + bb.z, h.w * nrm + bb.w);
    ((float4*)g_acc)[idx] = o;
}

// one warp per edge; each lane handles 4 columns -> 4 scalar float atomics
__global__ void k_edge(const void* __restrict__ ei) {
    int lane = threadIdx.x & 31;
    int warp = (blockIdx.x * blockDim.x + threadIdx.x) >> 5;
    int nwarps = (gridDim.x * blockDim.x) >> 5;
    for (int e = warp; e < EE; e += nwarps) {
        int src = load_src(ei, e);
        int dst = load_dst(ei, e);
        if ((unsigned)src >= NN || (unsigned)dst >= NN) continue;
        float nrm = g_dinv[src] * g_dinv[dst];
        float4 v = ((const float4*)(g_h + (size_t)src * DD))[lane];
        float* p = g_acc + (size_t)dst * DD + lane * 4;
        atomicAdd(p + 0, v.x * nrm);
        atomicAdd(p + 1, v.y * nrm);
        atomicAdd(p + 2, v.z * nrm);
        atomicAdd(p + 3, v.w * nrm);
    }
}

// per-column sum and sum-of-squares (256 threads = 2 rows per iter)
__global__ void k_colsum() {
    int col = threadIdx.x & 127;
    int sub = threadIdx.x >> 7;   // 0..1
    float s = 0.f, s2 = 0.f;
    for (int r = blockIdx.x * 2 + sub; r < NN; r += gridDim.x * 2) {
        float v = g_acc[(size_t)r * DD + col];
        s += v; s2 += v * v;
    }
    atomicAdd(&g_colsum[col], s);
    atomicAdd(&g_colsumsq[col], s2);
}

__global__ void k_bnparam(const float* __restrict__ gamma, const float* __restrict__ beta) {
    int c = threadIdx.x;
    if (c >= DD) return;
    float mean = g_colsum[c] * (1.0f / (float)NN);
    float var  = g_colsumsq[c] * (1.0f / (float)NN) - mean * mean;
    float rstd = rsqrtf(var + 1e-5f);
    float sc   = rstd * gamma[c];
    g_scale[c] = sc;
    g_shift[c] = beta[c] - mean * sc;
}

// out = relu(acc*scale + shift) + x
__global__ void k_final(const float* __restrict__ X, float* __restrict__ out) {
    int idx = blockIdx.x * blockDim.x + threadIdx.x;
    if (idx >= NN * 32) return;
    int c4 = idx & 31;
    float4 a  = ((const float4*)g_acc)[idx];
    float4 sc = ((const float4*)g_scale)[c4];
    float4 sh = ((const float4*)g_shift)[c4];
    float4 xv = ((const float4*)X)[idx];
    float4 o;
    o.x = fmaxf(a.x * sc.x + sh.x, 0.f) + xv.x;
    o.y = fmaxf(a.y * sc.y + sh.y, 0.f) + xv.y;
    o.z = fmaxf(a.z * sc.z + sh.z, 0.f) + xv.z;
    o.w = fmaxf(a.w * sc.w + sh.w, 0.f) + xv.w;
    ((float4*)out)[idx] = o;
}

// ---------------- launch ----------------
extern "C" void kernel_launch(void* const* d_in, const int* in_sizes, int n_in,
                              void* d_out, int out_size) {
    // Identify inputs by element count (robust to metadata ordering):
    //   x: 12,800,000   edge_index: 1,200,000   W: 16,384
    //   b, gamma, beta: 128 each (taken in encounter order)
    const float* x     = nullptr;
    const void*  ei    = nullptr;
    const float* W     = nullptr;
    const float* b     = nullptr;
    const float* gamma = nullptr;
    const float* beta  = nullptr;
    for (int i = 0; i < n_in; i++) {
        int sz = in_sizes[i];
        if (sz == NN * DD)        { x  = (const float*)d_in[i]; }
        else if (sz == 2 * EE)    { ei = d_in[i]; }
        else if (sz == DD * DD)   { W  = (const float*)d_in[i]; }
        else if (sz == DD) {
            if (!b) b = (const float*)d_in[i];
            else if (!gamma) gamma = (const float*)d_in[i];
            else beta = (const float*)d_in[i];
        }
    }
    float* out = (float*)d_out;

    k_detect<<<1, 32>>>(ei);
    k_zero<<<(NN + 255) / 256, 256>>>();
    k_degree<<<(EE + 255) / 256, 256>>>(ei);
    k_dinv<<<(NN + 255) / 256, 256>>>();
    k_gemm<<<(NN + 63) / 64, 256>>>(x, W);
    k_init<<<(NN * 32 + 255) / 256, 256>>>(b);
    k_edge<<<2048, 256>>>(ei);
    k_colsum<<<1024, 256>>>();
    k_bnparam<<<1, 128>>>(gamma, beta);
    k_final<<<(NN * 32 + 255) / 256, 256>>>(x, out);
}

// round 5
// speedup vs baseline: 1.3491x; 1.3491x over previous
#include <cuda_runtime.h>

#define NN 100000
#define EE 600000
#define DD 128

typedef unsigned long long u64;

// ---------------- scratch (static __device__, no allocation) ----------------
__device__ float g_h[(size_t)NN * DD];     // x @ W
__device__ float g_acc[(size_t)NN * DD];   // aggregated messages
__device__ float g_dinv[NN];
__device__ int   g_deg[NN];
__device__ int   g_rowstart[NN];
__device__ int   g_pos[NN];
__device__ int   g_bsum[128];
__device__ int   g_boff[128];
__device__ int2  g_emeta[EE];              // {src, bitcast(norm)}
__device__ float g_colsum[DD];
__device__ float g_colsumsq[DD];
__device__ float g_scale[DD];
__device__ float g_shift[DD];
__device__ int   g_ei32;                   // 1 if edge_index stored as int32

// ---------------- f32x2 helpers ----------------
__device__ __forceinline__ u64 pack2(float lo, float hi) {
    u64 r; asm("mov.b64 %0, {%1, %2};" : "=l"(r) : "f"(lo), "f"(hi)); return r;
}
__device__ __forceinline__ void unpack2(u64 v, float& lo, float& hi) {
    asm("mov.b64 {%0, %1}, %2;" : "=f"(lo), "=f"(hi) : "l"(v));
}
__device__ __forceinline__ u64 fma2(u64 a, u64 b, u64 c) {
    u64 d; asm("fma.rn.f32x2 %0, %1, %2, %3;" : "=l"(d) : "l"(a), "l"(b), "l"(c)); return d;
}

// ---------------- edge index decode ----------------
__device__ __forceinline__ int load_src(const void* ei, int e) {
    return g_ei32 ? ((const int*)ei)[e] : (int)((const long long*)ei)[e];
}
__device__ __forceinline__ int load_dst(const void* ei, int e) {
    return g_ei32 ? ((const int*)ei)[EE + e] : (int)((const long long*)ei)[EE + e];
}

// parallel dtype sniff: 1024 threads check 1024 int64-decoded entries
__global__ void k_detect(const void* ei) {
    const long long* p = (const long long*)ei;
    long long v = p[threadIdx.x];
    unsigned bad = __ballot_sync(0xFFFFFFFFu, v < 0 || v >= NN);
    __shared__ int s_bad;
    if (threadIdx.x == 0) s_bad = 0;
    __syncthreads();
    if (bad && (threadIdx.x & 31) == 0) atomicOr(&s_bad, 1);
    __syncthreads();
    if (threadIdx.x == 0) g_ei32 = s_bad;
}

__global__ void k_zero() {
    int i = blockIdx.x * blockDim.x + threadIdx.x;
    if (i < NN) g_deg[i] = 0;
    if (i < DD) { g_colsum[i] = 0.f; g_colsumsq[i] = 0.f; }
}

__global__ void k_degree(const void* __restrict__ ei) {
    int i = blockIdx.x * blockDim.x + threadIdx.x;
    if (i < EE) {
        int d = load_dst(ei, i);
        if ((unsigned)d < NN) atomicAdd(&g_deg[d], 1);
    }
}

// ---------------- exclusive scan of deg -> rowstart ----------------
__global__ void k_scan1() {        // 98 blocks x 1024 threads
    __shared__ int s[1024];
    int t = threadIdx.x;
    int i = blockIdx.x * 1024 + t;
    int v = (i < NN) ? g_deg[i] : 0;
    s[t] = v;
    __syncthreads();
#pragma unroll
    for (int off = 1; off < 1024; off <<= 1) {
        int add = (t >= off) ? s[t - off] : 0;
        __syncthreads();
        s[t] += add;
        __syncthreads();
    }
    if (i < NN) g_rowstart[i] = s[t] - v;    // exclusive within block
    if (t == 1023) g_bsum[blockIdx.x] = s[1023];
}

__global__ void k_scan2(int nblk) {            // 1 block, 128 threads
    __shared__ int s[128];
    int t = threadIdx.x;
    s[t] = (t < nblk) ? g_bsum[t] : 0;
    __syncthreads();
    if (t == 0) {
        int run = 0;
        for (int b = 0; b < nblk; b++) { g_boff[b] = run; run += s[b]; }
    }
}

// add block offsets; also compute dinv (deg + self-loop)
__global__ void k_scan3() {
    int i = blockIdx.x * blockDim.x + threadIdx.x;
    if (i < NN) {
        int rs = g_rowstart[i] + g_boff[i >> 10];
        g_rowstart[i] = rs;
        g_pos[i] = rs;
        g_dinv[i] = rsqrtf((float)g_deg[i] + 1.0f);
    }
}

// fill CSR edge meta: {src, norm}
__global__ void k_fill(const void* __restrict__ ei) {
    int e = blockIdx.x * blockDim.x + threadIdx.x;
    if (e >= EE) return;
    int src = load_src(ei, e);
    int dst = load_dst(ei, e);
    if ((unsigned)src >= NN || (unsigned)dst >= NN) return;
    float nrm = g_dinv[src] * g_dinv[dst];
    int slot = atomicAdd(&g_pos[dst], 1);
    g_emeta[slot] = make_int2(src, __float_as_int(nrm));
}

// ---------------- GEMM: h = X @ W via packed fma.rn.f32x2 ----------------
// 64 rows x 128 cols per block, four K-chunks of 32. 256 threads.
__global__ void k_gemm(const float* __restrict__ X, const float* __restrict__ W) {
    __shared__ float Ws[32 * 128];
    __shared__ float xs[32 * 68];
    const int tid = threadIdx.x;
    const int tx  = tid & 31;     // cols tx*4..tx*4+3
    const int ty  = tid >> 5;     // rows ty*8..ty*8+7
    const int rowBase = blockIdx.x * 64;

    u64 acc2[4][4];               // [rowpair p -> rows 2p,2p+1][col j]
#pragma unroll
    for (int p = 0; p < 4; p++)
#pragma unroll
        for (int j = 0; j < 4; j++) acc2[p][j] = 0ull;

    for (int kc = 0; kc < 4; kc++) {
        __syncthreads();
        const float4* Wg = (const float4*)(W + (size_t)kc * 32 * DD);
        float4* Ws4 = (float4*)Ws;
#pragma unroll
        for (int i = 0; i < 4; i++) Ws4[tid + 256 * i] = Wg[tid + 256 * i];
#pragma unroll
        for (int i = 0; i < 8; i++) {
            int idx = tid + 256 * i;
            int r = idx >> 5;
            int k = idx & 31;
            int row = rowBase + r;
            xs[k * 68 + r] = (row < NN) ? X[(size_t)row * DD + kc * 32 + k] : 0.f;
        }
        __syncthreads();
#pragma unroll
        for (int k = 0; k < 32; k++) {
            float4 wv = ((const float4*)(Ws + k * DD))[tx];
            u64 w2[4] = {pack2(wv.x, wv.x), pack2(wv.y, wv.y),
                         pack2(wv.z, wv.z), pack2(wv.w, wv.w)};
            float4 xa = *(const float4*)(xs + k * 68 + ty * 8);
            float4 xb = *(const float4*)(xs + k * 68 + ty * 8 + 4);
            u64 x2[4] = {pack2(xa.x, xa.y), pack2(xa.z, xa.w),
                         pack2(xb.x, xb.y), pack2(xb.z, xb.w)};
#pragma unroll
            for (int p = 0; p < 4; p++)
#pragma unroll
                for (int j = 0; j < 4; j++)
                    acc2[p][j] = fma2(x2[p], w2[j], acc2[p][j]);
        }
    }
#pragma unroll
    for (int p = 0; p < 4; p++) {
        float lo[4], hi[4];
#pragma unroll
        for (int j = 0; j < 4; j++) unpack2(acc2[p][j], lo[j], hi[j]);
        int row0 = rowBase + ty * 8 + 2 * p;
        if (row0 < NN)
            ((float4*)(g_h + (size_t)row0 * DD))[tx] = make_float4(lo[0], lo[1], lo[2], lo[3]);
        if (row0 + 1 < NN)
            ((float4*)(g_h + (size_t)(row0 + 1) * DD))[tx] = make_float4(hi[0], hi[1], hi[2], hi[3]);
    }
}

// ---------------- gather: warp per dst node, fused init + BN stats -------
__global__ void k_gather(const float* __restrict__ b) {
    __shared__ float s_sum[DD];
    __shared__ float s_sumsq[DD];
    int t = threadIdx.x;
    if (t < DD) { s_sum[t] = 0.f; s_sumsq[t] = 0.f; }
    __syncthreads();

    int lane = t & 31;
    int node = blockIdx.x * 8 + (t >> 5);
    if (node < NN) {
        float dv = g_dinv[node];
        float4 hv = ((const float4*)(g_h + (size_t)node * DD))[lane];
        float4 bb = ((const float4*)b)[lane];
        float nrm0 = dv * dv;
        float4 a = make_float4(hv.x * nrm0 + bb.x, hv.y * nrm0 + bb.y,
                               hv.z * nrm0 + bb.z, hv.w * nrm0 + bb.w);
        int e   = g_rowstart[node];
        int end = e + g_deg[node];
        for (; e < end; e++) {
            int2 m = g_emeta[e];                       // warp-uniform broadcast
            float nrm = __int_as_float(m.y);
            float4 v = ((const float4*)(g_h + (size_t)m.x * DD))[lane];
            a.x += v.x * nrm; a.y += v.y * nrm;
            a.z += v.z * nrm; a.w += v.w * nrm;
        }
        ((float4*)(g_acc + (size_t)node * DD))[lane] = a;
        int c = lane * 4;
        atomicAdd(&s_sum[c + 0], a.x); atomicAdd(&s_sumsq[c + 0], a.x * a.x);
        atomicAdd(&s_sum[c + 1], a.y); atomicAdd(&s_sumsq[c + 1], a.y * a.y);
        atomicAdd(&s_sum[c + 2], a.z); atomicAdd(&s_sumsq[c + 2], a.z * a.z);
        atomicAdd(&s_sum[c + 3], a.w); atomicAdd(&s_sumsq[c + 3], a.w * a.w);
    }
    __syncthreads();
    if (t < DD)            atomicAdd(&g_colsum[t], s_sum[t]);
    else if (t < 2 * DD)   atomicAdd(&g_colsumsq[t - DD], s_sumsq[t - DD]);
}

__global__ void k_bnparam(const float* __restrict__ gamma, const float* __restrict__ beta) {
    int c = threadIdx.x;
    if (c >= DD) return;
    float mean = g_colsum[c] * (1.0f / (float)NN);
    float var  = g_colsumsq[c] * (1.0f / (float)NN) - mean * mean;
    float rstd = rsqrtf(var + 1e-5f);
    float sc   = rstd * gamma[c];
    g_scale[c] = sc;
    g_shift[c] = beta[c] - mean * sc;
}

// out = relu(acc*scale + shift) + x
__global__ void k_final(const float* __restrict__ X, float* __restrict__ out) {
    int idx = blockIdx.x * blockDim.x + threadIdx.x;
    if (idx >= NN * 32) return;
    int c4 = idx & 31;
    float4 a  = ((const float4*)g_acc)[idx];
    float4 sc = ((const float4*)g_scale)[c4];
    float4 sh = ((const float4*)g_shift)[c4];
    float4 xv = ((const float4*)X)[idx];
    float4 o;
    o.x = fmaxf(a.x * sc.x + sh.x, 0.f) + xv.x;
    o.y = fmaxf(a.y * sc.y + sh.y, 0.f) + xv.y;
    o.z = fmaxf(a.z * sc.z + sh.z, 0.f) + xv.z;
    o.w = fmaxf(a.w * sc.w + sh.w, 0.f) + xv.w;
    ((float4*)out)[idx] = o;
}

// ---------------- launch ----------------
extern "C" void kernel_launch(void* const* d_in, const int* in_sizes, int n_in,
                              void* d_out, int out_size) {
    // bind inputs by element count (robust to metadata ordering)
    const float* x = nullptr; const void* ei = nullptr; const float* W = nullptr;
    const float* b = nullptr; const float* gamma = nullptr; const float* beta = nullptr;
    for (int i = 0; i < n_in; i++) {
        int sz = in_sizes[i];
        if (sz == NN * DD)      x  = (const float*)d_in[i];
        else if (sz == 2 * EE)  ei = d_in[i];
        else if (sz == DD * DD) W  = (const float*)d_in[i];
        else if (sz == DD) {
            if (!b) b = (const float*)d_in[i];
            else if (!gamma) gamma = (const float*)d_in[i];
            else beta = (const float*)d_in[i];
        }
    }
    float* out = (float*)d_out;

    const int SCAN_BLOCKS = (NN + 1023) / 1024;   // 98

    k_detect<<<1, 1024>>>(ei);
    k_zero<<<(NN + 255) / 256, 256>>>();
    k_degree<<<(EE + 255) / 256, 256>>>(ei);
    k_scan1<<<SCAN_BLOCKS, 1024>>>();
    k_scan2<<<1, 128>>>(SCAN_BLOCKS);
    k_scan3<<<(NN + 255) / 256, 256>>>();
    k_gemm<<<(NN + 63) / 64, 256>>>(x, W);
    k_fill<<<(EE + 255) / 256, 256>>>(ei);
    k_gather<<<(NN + 7) / 8, 256>>>(b);
    k_bnparam<<<1, 128>>>(gamma, beta);
    k_final<<<(NN * 32 + 255) / 256, 256>>>(x, out);
}

// round 7
// speedup vs baseline: 1.3783x; 1.0217x over previous
#include <cuda_runtime.h>

#define NN 100000
#define EE 600000
#define DD 128

typedef unsigned long long u64;

// ---------------- scratch (static __device__, no allocation) ----------------
__device__ float g_h[(size_t)NN * DD];     // x @ W
__device__ float g_acc[(size_t)NN * DD];   // aggregated messages
__device__ float g_dinv[NN];
__device__ int   g_deg[NN];
__device__ int   g_rowstart[NN];
__device__ int   g_pos[NN];
__device__ int   g_bsum[128];
__device__ int   g_boff[128];
__device__ int2  g_emeta[EE];              // {src, bitcast(norm)}
__device__ float g_colsum[DD];
__device__ float g_colsumsq[DD];
__device__ float g_scale[DD];
__device__ float g_shift[DD];
__device__ int   g_ei32;                   // 1 if edge_index stored as int32

// ---------------- f32x2 helpers ----------------
__device__ __forceinline__ u64 pack2(float lo, float hi) {
    u64 r; asm("mov.b64 %0, {%1, %2};" : "=l"(r) : "f"(lo), "f"(hi)); return r;
}
__device__ __forceinline__ void unpack2(u64 v, float& lo, float& hi) {
    asm("mov.b64 {%0, %1}, %2;" : "=f"(lo), "=f"(hi) : "l"(v));
}
__device__ __forceinline__ u64 fma2(u64 a, u64 b, u64 c) {
    u64 d; asm("fma.rn.f32x2 %0, %1, %2, %3;" : "=l"(d) : "l"(a), "l"(b), "l"(c)); return d;
}

// ---------------- edge index decode ----------------
__device__ __forceinline__ int load_src(const void* ei, int e) {
    return g_ei32 ? ((const int*)ei)[e] : (int)((const long long*)ei)[e];
}
__device__ __forceinline__ int load_dst(const void* ei, int e) {
    return g_ei32 ? ((const int*)ei)[EE + e] : (int)((const long long*)ei)[EE + e];
}

// parallel dtype sniff: 1024 threads check 1024 int64-decoded entries
__global__ void k_detect(const void* ei) {
    const long long* p = (const long long*)ei;
    long long v = p[threadIdx.x];
    unsigned bad = __ballot_sync(0xFFFFFFFFu, v < 0 || v >= NN);
    __shared__ int s_bad;
    if (threadIdx.x == 0) s_bad = 0;
    __syncthreads();
    if (bad && (threadIdx.x & 31) == 0) atomicOr(&s_bad, 1);
    __syncthreads();
    if (threadIdx.x == 0) g_ei32 = s_bad;
}

__global__ void k_zero() {
    int i = blockIdx.x * blockDim.x + threadIdx.x;
    if (i < NN) g_deg[i] = 0;
    if (i < DD) { g_colsum[i] = 0.f; g_colsumsq[i] = 0.f; }
}

__global__ void k_degree(const void* __restrict__ ei) {
    int i = blockIdx.x * blockDim.x + threadIdx.x;
    if (i < EE) {
        int d = load_dst(ei, i);
        if ((unsigned)d < NN) atomicAdd(&g_deg[d], 1);
    }
}

// ---------------- exclusive scan of deg -> rowstart (shfl-based) ----------
__global__ void k_scan1() {        // 98 blocks x 1024 threads
    __shared__ int s_warp[32];
    int t = threadIdx.x;
    int lane = t & 31;
    int wid = t >> 5;
    int i = blockIdx.x * 1024 + t;
    int v = (i < NN) ? g_deg[i] : 0;
    // inclusive scan within warp
    int sc = v;
#pragma unroll
    for (int off = 1; off < 32; off <<= 1) {
        int n = __shfl_up_sync(0xFFFFFFFFu, sc, off);
        if (lane >= off) sc += n;
    }
    if (lane == 31) s_warp[wid] = sc;
    __syncthreads();
    if (wid == 0) {
        int ws = s_warp[lane];
#pragma unroll
        for (int off = 1; off < 32; off <<= 1) {
            int n = __shfl_up_sync(0xFFFFFFFFu, ws, off);
            if (lane >= off) ws += n;
        }
        s_warp[lane] = ws;
    }
    __syncthreads();
    int base = (wid > 0) ? s_warp[wid - 1] : 0;
    if (i < NN) g_rowstart[i] = base + sc - v;   // exclusive within block
    if (t == 1023) g_bsum[blockIdx.x] = base + sc;
}

__global__ void k_scan2(int nblk) {            // 1 block
    int t = threadIdx.x;
    if (t == 0) {
        int run = 0;
        for (int b = 0; b < nblk; b++) { g_boff[b] = run; run += g_bsum[b]; }
    }
}

// add block offsets; also compute dinv (deg + self-loop)
__global__ void k_scan3() {
    int i = blockIdx.x * blockDim.x + threadIdx.x;
    if (i < NN) {
        int rs = g_rowstart[i] + g_boff[i >> 10];
        g_rowstart[i] = rs;
        g_pos[i] = rs;
        g_dinv[i] = rsqrtf((float)g_deg[i] + 1.0f);
    }
}

// fill CSR edge meta: {src, norm}
__global__ void k_fill(const void* __restrict__ ei) {
    int e = blockIdx.x * blockDim.x + threadIdx.x;
    if (e >= EE) return;
    int src = load_src(ei, e);
    int dst = load_dst(ei, e);
    if ((unsigned)src >= NN || (unsigned)dst >= NN) return;
    float nrm = g_dinv[src] * g_dinv[dst];
    int slot = atomicAdd(&g_pos[dst], 1);
    g_emeta[slot] = make_int2(src, __float_as_int(nrm));
}

// ---------------- GEMM: h = X @ W via packed fma.rn.f32x2 ----------------
// 64 rows x 128 cols per block, four K-chunks of 32. 256 threads.
__global__ void k_gemm(const float* __restrict__ X, const float* __restrict__ W) {
    __shared__ float Ws[32 * 128];
    __shared__ float xs[32 * 68];
    const int tid = threadIdx.x;
    const int tx  = tid & 31;     // cols tx*4..tx*4+3
    const int ty  = tid >> 5;     // rows ty*8..ty*8+7
    const int rowBase = blockIdx.x * 64;

    u64 acc2[4][4];               // [rowpair p -> rows 2p,2p+1][col j]
#pragma unroll
    for (int p = 0; p < 4; p++)
#pragma unroll
        for (int j = 0; j < 4; j++) acc2[p][j] = 0ull;

    for (int kc = 0; kc < 4; kc++) {
        __syncthreads();
        const float4* Wg = (const float4*)(W + (size_t)kc * 32 * DD);
        float4* Ws4 = (float4*)Ws;
#pragma unroll
        for (int i = 0; i < 4; i++) Ws4[tid + 256 * i] = Wg[tid + 256 * i];
#pragma unroll
        for (int i = 0; i < 8; i++) {
            int idx = tid + 256 * i;
            int r = idx >> 5;
            int k = idx & 31;
            int row = rowBase + r;
            xs[k * 68 + r] = (row < NN) ? X[(size_t)row * DD + kc * 32 + k] : 0.f;
        }
        __syncthreads();
#pragma unroll
        for (int k = 0; k < 32; k++) {
            float4 wv = ((const float4*)(Ws + k * DD))[tx];
            u64 w2[4] = {pack2(wv.x, wv.x), pack2(wv.y, wv.y),
                         pack2(wv.z, wv.z), pack2(wv.w, wv.w)};
            float4 xa = *(const float4*)(xs + k * 68 + ty * 8);
            float4 xb = *(const float4*)(xs + k * 68 + ty * 8 + 4);
            u64 x2[4] = {pack2(xa.x, xa.y), pack2(xa.z, xa.w),
                         pack2(xb.x, xb.y), pack2(xb.z, xb.w)};
#pragma unroll
            for (int p = 0; p < 4; p++)
#pragma unroll
                for (int j = 0; j < 4; j++)
                    acc2[p][j] = fma2(x2[p], w2[j], acc2[p][j]);
        }
    }
#pragma unroll
    for (int p = 0; p < 4; p++) {
        float lo[4], hi[4];
#pragma unroll
        for (int j = 0; j < 4; j++) unpack2(acc2[p][j], lo[j], hi[j]);
        int row0 = rowBase + ty * 8 + 2 * p;
        if (row0 < NN)
            ((float4*)(g_h + (size_t)row0 * DD))[tx] = make_float4(lo[0], lo[1], lo[2], lo[3]);
        if (row0 + 1 < NN)
            ((float4*)(g_h + (size_t)(row0 + 1) * DD))[tx] = make_float4(hi[0], hi[1], hi[2], hi[3]);
    }
}

// ---------------- gather: warp per dst node, fused init + BN stats -------
// 2-edge software pipeline for memory-level parallelism.
__global__ void k_gather(const float* __restrict__ b) {
    __shared__ float s_sum[DD];
    __shared__ float s_sumsq[DD];
    int t = threadIdx.x;
    if (t < DD) { s_sum[t] = 0.f; s_sumsq[t] = 0.f; }
    __syncthreads();

    int lane = t & 31;
    int node = blockIdx.x * 8 + (t >> 5);
    if (node < NN) {
        float dv = g_dinv[node];
        float4 hv = ((const float4*)(g_h + (size_t)node * DD))[lane];
        float4 bb = ((const float4*)b)[lane];
        float nrm0 = dv * dv;
        float4 a = make_float4(hv.x * nrm0 + bb.x, hv.y * nrm0 + bb.y,
                               hv.z * nrm0 + bb.z, hv.w * nrm0 + bb.w);
        int e   = g_rowstart[node];
        int end = e + g_deg[node];
        for (; e + 1 < end; e += 2) {
            int2 m0 = g_emeta[e];
            int2 m1 = g_emeta[e + 1];
            float4 v0 = ((const float4*)(g_h + (size_t)m0.x * DD))[lane];
            float4 v1 = ((const float4*)(g_h + (size_t)m1.x * DD))[lane];
            float n0 = __int_as_float(m0.y);
            float n1 = __int_as_float(m1.y);
            a.x += v0.x * n0; a.y += v0.y * n0; a.z += v0.z * n0; a.w += v0.w * n0;
            a.x += v1.x * n1; a.y += v1.y * n1; a.z += v1.z * n1; a.w += v1.w * n1;
        }
        if (e < end) {
            int2 m = g_emeta[e];
            float nrm = __int_as_float(m.y);
            float4 v = ((const float4*)(g_h + (size_t)m.x * DD))[lane];
            a.x += v.x * nrm; a.y += v.y * nrm;
            a.z += v.z * nrm; a.w += v.w * nrm;
        }
        ((float4*)(g_acc + (size_t)node * DD))[lane] = a;
        int c = lane * 4;
        atomicAdd(&s_sum[c + 0], a.x); atomicAdd(&s_sumsq[c + 0], a.x * a.x);
        atomicAdd(&s_sum[c + 1], a.y); atomicAdd(&s_sumsq[c + 1], a.y * a.y);
        atomicAdd(&s_sum[c + 2], a.z); atomicAdd(&s_sumsq[c + 2], a.z * a.z);
        atomicAdd(&s_sum[c + 3], a.w); atomicAdd(&s_sumsq[c + 3], a.w * a.w);
    }
    __syncthreads();
    if (t < DD)            atomicAdd(&g_colsum[t], s_sum[t]);
    else if (t < 2 * DD)   atomicAdd(&g_colsumsq[t - DD], s_sumsq[t - DD]);
}

__global__ void k_bnparam(const float* __restrict__ gamma, const float* __restrict__ beta) {
    int c = threadIdx.x;
    if (c >= DD) return;
    float mean = g_colsum[c] * (1.0f / (float)NN);
    float var  = g_colsumsq[c] * (1.0f / (float)NN) - mean * mean;
    float rstd = rsqrtf(var + 1e-5f);
    float sc   = rstd * gamma[c];
    g_scale[c] = sc;
    g_shift[c] = beta[c] - mean * sc;
}

// out = relu(acc*scale + shift) + x
__global__ void k_final(const float* __restrict__ X, float* __restrict__ out) {
    int idx = blockIdx.x * blockDim.x + threadIdx.x;
    if (idx >= NN * 32) return;
    int c4 = idx & 31;
    float4 a  = ((const float4*)g_acc)[idx];
    float4 sc = ((const float4*)g_scale)[c4];
    float4 sh = ((const float4*)g_shift)[c4];
    float4 xv = ((const float4*)X)[idx];
    float4 o;
    o.x = fmaxf(a.x * sc.x + sh.x, 0.f) + xv.x;
    o.y = fmaxf(a.y * sc.y + sh.y, 0.f) + xv.y;
    o.z = fmaxf(a.z * sc.z + sh.z, 0.f) + xv.z;
    o.w = fmaxf(a.w * sc.w + sh.w, 0.f) + xv.w;
    ((float4*)out)[idx] = o;
}

// ---------------- launch ----------------
extern "C" void kernel_launch(void* const* d_in, const int* in_sizes, int n_in,
                              void* d_out, int out_size) {
    // bind inputs by element count (robust to metadata ordering)
    const float* x = nullptr; const void* ei = nullptr; const float* W = nullptr;
    const float* b = nullptr; const float* gamma = nullptr; const float* beta = nullptr;
    for (int i = 0; i < n_in; i++) {
        int sz = in_sizes[i];
        if (sz == NN * DD)      x  = (const float*)d_in[i];
        else if (sz == 2 * EE)  ei = d_in[i];
        else if (sz == DD * DD) W  = (const float*)d_in[i];
        else if (sz == DD) {
            if (!b) b = (const float*)d_in[i];
            else if (!gamma) gamma = (const float*)d_in[i];
            else beta = (const float*)d_in[i];
        }
    }
    float* out = (float*)d_out;

    const int SCAN_BLOCKS = (NN + 1023) / 1024;   // 98

    // Lazy-create side stream + fork/join events once (first call is the
    // uncaptured correctness run; reused identically during capture).
    static cudaStream_t s_side = nullptr;
    static cudaEvent_t ev_fork = nullptr, ev_join = nullptr;
    if (!s_side) {
        cudaStreamCreateWithFlags(&s_side, cudaStreamNonBlocking);
        cudaEventCreateWithFlags(&ev_fork, cudaEventDisableTiming);
        cudaEventCreateWithFlags(&ev_join, cudaEventDisableTiming);
    }

    // Fork: GEMM (x,W only) runs concurrently with the edge-prep chain.
    cudaEventRecord(ev_fork, 0);
    cudaStreamWaitEvent(s_side, ev_fork, 0);
    k_gemm<<<(NN + 63) / 64, 256, 0, s_side>>>(x, W);
    cudaEventRecord(ev_join, s_side);

    // Edge-prep chain on the main stream.
    k_detect<<<1, 1024>>>(ei);
    k_zero<<<(NN + 255) / 256, 256>>>();
    k_degree<<<(EE + 255) / 256, 256>>>(ei);
    k_scan1<<<SCAN_BLOCKS, 1024>>>();
    k_scan2<<<1, 32>>>(SCAN_BLOCKS);
    k_scan3<<<(NN + 255) / 256, 256>>>();
    k_fill<<<(EE + 255) / 256, 256>>>(ei);

    // Join: gather needs both h (gemm) and CSR (fill).
    cudaStreamWaitEvent(0, ev_join, 0);
    k_gather<<<(NN + 7) / 8, 256>>>(b);
    k_bnparam<<<1, 128>>>(gamma, beta);
    k_final<<<(NN * 32 + 255) / 256, 256>>>(x, out);
}

// round 9
// speedup vs baseline: 1.5302x; 1.1102x over previous
#include <cuda_runtime.h>

#define NN 100000
#define EE 600000
#define DD 128

typedef unsigned long long u64;

// ---------------- scratch (static __device__, no allocation) ----------------
__device__ float g_h[(size_t)NN * DD];     // x @ W
__device__ float g_acc[(size_t)NN * DD];   // aggregated messages
__device__ float g_dinv[NN];
__device__ int   g_deg[NN];
__device__ int   g_rowstart[NN];
__device__ int   g_pos[NN];
__device__ int   g_bsum[128];
__device__ int   g_boff[128];
__device__ int2  g_emeta[EE];              // {src, bitcast(norm)}
__device__ float g_colsum[DD];
__device__ float g_colsumsq[DD];
__device__ float g_scale[DD];
__device__ float g_shift[DD];
__device__ int   g_ei32;                   // 1 if edge_index stored as int32

// ---------------- edge index decode ----------------
__device__ __forceinline__ int load_src(const void* ei, int e) {
    return g_ei32 ? ((const int*)ei)[e] : (int)((const long long*)ei)[e];
}
__device__ __forceinline__ int load_dst(const void* ei, int e) {
    return g_ei32 ? ((const int*)ei)[EE + e] : (int)((const long long*)ei)[EE + e];
}

__global__ void k_detect(const void* ei) {
    const long long* p = (const long long*)ei;
    long long v = p[threadIdx.x];
    unsigned bad = __ballot_sync(0xFFFFFFFFu, v < 0 || v >= NN);
    __shared__ int s_bad;
    if (threadIdx.x == 0) s_bad = 0;
    __syncthreads();
    if (bad && (threadIdx.x & 31) == 0) atomicOr(&s_bad, 1);
    __syncthreads();
    if (threadIdx.x == 0) g_ei32 = s_bad;
}

__global__ void k_zero() {
    int i = blockIdx.x * blockDim.x + threadIdx.x;
    if (i < NN) g_deg[i] = 0;
    if (i < DD) { g_colsum[i] = 0.f; g_colsumsq[i] = 0.f; }
}

__global__ void k_degree(const void* __restrict__ ei) {
    int i = blockIdx.x * blockDim.x + threadIdx.x;
    if (i < EE) {
        int d = load_dst(ei, i);
        if ((unsigned)d < NN) atomicAdd(&g_deg[d], 1);
    }
}

// ---------------- exclusive scan of deg -> rowstart (shfl-based) ----------
__global__ void k_scan1() {        // 98 blocks x 1024 threads
    __shared__ int s_warp[32];
    int t = threadIdx.x;
    int lane = t & 31;
    int wid = t >> 5;
    int i = blockIdx.x * 1024 + t;
    int v = (i < NN) ? g_deg[i] : 0;
    int sc = v;
#pragma unroll
    for (int off = 1; off < 32; off <<= 1) {
        int n = __shfl_up_sync(0xFFFFFFFFu, sc, off);
        if (lane >= off) sc += n;
    }
    if (lane == 31) s_warp[wid] = sc;
    __syncthreads();
    if (wid == 0) {
        int ws = s_warp[lane];
#pragma unroll
        for (int off = 1; off < 32; off <<= 1) {
            int n = __shfl_up_sync(0xFFFFFFFFu, ws, off);
            if (lane >= off) ws += n;
        }
        s_warp[lane] = ws;
    }
    __syncthreads();
    int base = (wid > 0) ? s_warp[wid - 1] : 0;
    if (i < NN) g_rowstart[i] = base + sc - v;
    if (t == 1023) g_bsum[blockIdx.x] = base + sc;
}

__global__ void k_scan2(int nblk) {
    if (threadIdx.x == 0) {
        int run = 0;
        for (int b = 0; b < nblk; b++) { g_boff[b] = run; run += g_bsum[b]; }
    }
}

__global__ void k_scan3() {
    int i = blockIdx.x * blockDim.x + threadIdx.x;
    if (i < NN) {
        int rs = g_rowstart[i] + g_boff[i >> 10];
        g_rowstart[i] = rs;
        g_pos[i] = rs;
        g_dinv[i] = rsqrtf((float)g_deg[i] + 1.0f);
    }
}

__global__ void k_fill(const void* __restrict__ ei) {
    int e = blockIdx.x * blockDim.x + threadIdx.x;
    if (e >= EE) return;
    int src = load_src(ei, e);
    int dst = load_dst(ei, e);
    if ((unsigned)src >= NN || (unsigned)dst >= NN) return;
    float nrm = g_dinv[src] * g_dinv[dst];
    int slot = atomicAdd(&g_pos[dst], 1);
    g_emeta[slot] = make_int2(src, __float_as_int(nrm));
}

// ---------------- GEMM: h = X @ W via mma.sync tf32 tensor cores ----------
// Block: 128 rows x 128 cols. 256 threads = 8 warps (2 M-halves x 4 N-quarters).
// Warp tile: 64 x 32 = 4 m16-tiles x 4 n8-tiles. K chunks of 32, 4 ksteps of 8.
__device__ __forceinline__ unsigned tf32cvt(float f) {
    unsigned r; asm("cvt.rna.tf32.f32 %0, %1;" : "=r"(r) : "f"(f)); return r;
}

__global__ void __launch_bounds__(256, 2)
k_gemm(const float* __restrict__ X, const float* __restrict__ W) {
    __shared__ unsigned Xs[128 * 36];   // [row][k] stride 36 (A-frag conflict-free)
    __shared__ unsigned Ws[32 * 136];   // [k][n]  stride 136 (B-frag conflict-free)
    const int tid  = threadIdx.x;
    const int lane = tid & 31;
    const int warp = tid >> 5;
    const int g    = lane >> 2;     // 0..7
    const int t4   = lane & 3;      // 0..3
    const int wm   = (warp & 1) * 64;    // M offset of warp tile
    const int wn   = (warp >> 1) * 32;   // N offset of warp tile
    const int rowBase = blockIdx.x * 128;

    float acc[4][4][4];             // [m-tile][n-tile][c0..c3]
#pragma unroll
    for (int i = 0; i < 4; i++)
#pragma unroll
        for (int j = 0; j < 4; j++)
#pragma unroll
            for (int c = 0; c < 4; c++) acc[i][j][c] = 0.f;

    for (int kc = 0; kc < 4; kc++) {
        __syncthreads();
        // stage W chunk [32 x 128] -> Ws (tf32-rounded)
#pragma unroll
        for (int i = 0; i < 16; i++) {
            int idx = tid + 256 * i;
            int kl = idx >> 7;          // 0..31
            int n  = idx & 127;
            Ws[kl * 136 + n] = tf32cvt(W[(size_t)(kc * 32 + kl) * DD + n]);
        }
        // stage X chunk [128 x 32] -> Xs (tf32-rounded)
#pragma unroll
        for (int i = 0; i < 16; i++) {
            int idx = tid + 256 * i;
            int r  = idx >> 5;          // 0..127
            int kl = idx & 31;
            int row = rowBase + r;
            float xv = (row < NN) ? X[(size_t)row * DD + kc * 32 + kl] : 0.f;
            Xs[r * 36 + kl] = tf32cvt(xv);
        }
        __syncthreads();
#pragma unroll
        for (int ks = 0; ks < 4; ks++) {
            const int kb = ks * 8;
            // B fragments: b[j][0]: (k=kb+t4, n=wn+j*8+g); b[j][1]: k+4
            unsigned bf[4][2];
#pragma unroll
            for (int j = 0; j < 4; j++) {
                int n = wn + j * 8 + g;
                bf[j][0] = Ws[(kb + t4) * 136 + n];
                bf[j][1] = Ws[(kb + t4 + 4) * 136 + n];
            }
            // A fragments per m-tile: a0:(g,t4) a1:(g+8,t4) a2:(g,t4+4) a3:(g+8,t4+4)
#pragma unroll
            for (int i = 0; i < 4; i++) {
                int r0 = wm + i * 16 + g;
                unsigned a0 = Xs[r0 * 36 + kb + t4];
                unsigned a1 = Xs[(r0 + 8) * 36 + kb + t4];
                unsigned a2 = Xs[r0 * 36 + kb + t4 + 4];
                unsigned a3 = Xs[(r0 + 8) * 36 + kb + t4 + 4];
#pragma unroll
                for (int j = 0; j < 4; j++) {
                    asm volatile(
                        "mma.sync.aligned.m16n8k8.row.col.f32.tf32.tf32.f32 "
                        "{%0,%1,%2,%3}, {%4,%5,%6,%7}, {%8,%9}, {%0,%1,%2,%3};"
                        : "+f"(acc[i][j][0]), "+f"(acc[i][j][1]),
                          "+f"(acc[i][j][2]), "+f"(acc[i][j][3])
                        : "r"(a0), "r"(a1), "r"(a2), "r"(a3),
                          "r"(bf[j][0]), "r"(bf[j][1]));
                }
            }
        }
    }
    // epilogue: c0,c1 -> (row g, cols 2t4,2t4+1); c2,c3 -> row g+8
#pragma unroll
    for (int i = 0; i < 4; i++) {
        int rbase = rowBase + wm + i * 16 + g;
#pragma unroll
        for (int half = 0; half < 2; half++) {
            int r = rbase + half * 8;
            if (r < NN) {
                float2* p = (float2*)(g_h + (size_t)r * DD + wn);
#pragma unroll
                for (int j = 0; j < 4; j++)
                    p[j * 4 + t4] = make_float2(acc[i][j][half * 2],
                                                acc[i][j][half * 2 + 1]);
            }
        }
    }
}

// ---------------- gather: warp per dst node, fused init + BN stats -------
__global__ void k_gather(const float* __restrict__ b) {
    __shared__ float s_sum[DD];
    __shared__ float s_sumsq[DD];
    int t = threadIdx.x;
    if (t < DD) { s_sum[t] = 0.f; s_sumsq[t] = 0.f; }
    __syncthreads();

    int lane = t & 31;
    int node = blockIdx.x * 8 + (t >> 5);
    if (node < NN) {
        float dv = g_dinv[node];
        float4 hv = ((const float4*)(g_h + (size_t)node * DD))[lane];
        float4 bb = ((const float4*)b)[lane];
        float nrm0 = dv * dv;
        float4 a = make_float4(hv.x * nrm0 + bb.x, hv.y * nrm0 + bb.y,
                               hv.z * nrm0 + bb.z, hv.w * nrm0 + bb.w);
        int e   = g_rowstart[node];
        int end = e + g_deg[node];
        for (; e + 1 < end; e += 2) {
            int2 m0 = g_emeta[e];
            int2 m1 = g_emeta[e + 1];
            float4 v0 = ((const float4*)(g_h + (size_t)m0.x * DD))[lane];
            float4 v1 = ((const float4*)(g_h + (size_t)m1.x * DD))[lane];
            float n0 = __int_as_float(m0.y);
            float n1 = __int_as_float(m1.y);
            a.x += v0.x * n0; a.y += v0.y * n0; a.z += v0.z * n0; a.w += v0.w * n0;
            a.x += v1.x * n1; a.y += v1.y * n1; a.z += v1.z * n1; a.w += v1.w * n1;
        }
        if (e < end) {
            int2 m = g_emeta[e];
            float nrm = __int_as_float(m.y);
            float4 v = ((const float4*)(g_h + (size_t)m.x * DD))[lane];
            a.x += v.x * nrm; a.y += v.y * nrm;
            a.z += v.z * nrm; a.w += v.w * nrm;
        }
        ((float4*)(g_acc + (size_t)node * DD))[lane] = a;
        int c = lane * 4;
        atomicAdd(&s_sum[c + 0], a.x); atomicAdd(&s_sumsq[c + 0], a.x * a.x);
        atomicAdd(&s_sum[c + 1], a.y); atomicAdd(&s_sumsq[c + 1], a.y * a.y);
        atomicAdd(&s_sum[c + 2], a.z); atomicAdd(&s_sumsq[c + 2], a.z * a.z);
        atomicAdd(&s_sum[c + 3], a.w); atomicAdd(&s_sumsq[c + 3], a.w * a.w);
    }
    __syncthreads();
    if (t < DD)            atomicAdd(&g_colsum[t], s_sum[t]);
    else if (t < 2 * DD)   atomicAdd(&g_colsumsq[t - DD], s_sumsq[t - DD]);
}

__global__ void k_bnparam(const float* __restrict__ gamma, const float* __restrict__ beta) {
    int c = threadIdx.x;
    if (c >= DD) return;
    float mean = g_colsum[c] * (1.0f / (float)NN);
    float var  = g_colsumsq[c] * (1.0f / (float)NN) - mean * mean;
    float rstd = rsqrtf(var + 1e-5f);
    float sc   = rstd * gamma[c];
    g_scale[c] = sc;
    g_shift[c] = beta[c] - mean * sc;
}

__global__ void k_final(const float* __restrict__ X, float* __restrict__ out) {
    int idx = blockIdx.x * blockDim.x + threadIdx.x;
    if (idx >= NN * 32) return;
    int c4 = idx & 31;
    float4 a  = ((const float4*)g_acc)[idx];
    float4 sc = ((const float4*)g_scale)[c4];
    float4 sh = ((const float4*)g_shift)[c4];
    float4 xv = ((const float4*)X)[idx];
    float4 o;
    o.x = fmaxf(a.x * sc.x + sh.x, 0.f) + xv.x;
    o.y = fmaxf(a.y * sc.y + sh.y, 0.f) + xv.y;
    o.z = fmaxf(a.z * sc.z + sh.z, 0.f) + xv.z;
    o.w = fmaxf(a.w * sc.w + sh.w, 0.f) + xv.w;
    ((float4*)out)[idx] = o;
}

// ---------------- launch ----------------
extern "C" void kernel_launch(void* const* d_in, const int* in_sizes, int n_in,
                              void* d_out, int out_size) {
    const float* x = nullptr; const void* ei = nullptr; const float* W = nullptr;
    const float* b = nullptr; const float* gamma = nullptr; const float* beta = nullptr;
    for (int i = 0; i < n_in; i++) {
        int sz = in_sizes[i];
        if (sz == NN * DD)      x  = (const float*)d_in[i];
        else if (sz == 2 * EE)  ei = d_in[i];
        else if (sz == DD * DD) W  = (const float*)d_in[i];
        else if (sz == DD) {
            if (!b) b = (const float*)d_in[i];
            else if (!gamma) gamma = (const float*)d_in[i];
            else beta = (const float*)d_in[i];
        }
    }
    float* out = (float*)d_out;

    const int SCAN_BLOCKS = (NN + 1023) / 1024;   // 98

    static cudaStream_t s_side = nullptr;
    static cudaEvent_t ev_fork = nullptr, ev_join = nullptr;
    if (!s_side) {
        cudaStreamCreateWithFlags(&s_side, cudaStreamNonBlocking);
        cudaEventCreateWithFlags(&ev_fork, cudaEventDisableTiming);
        cudaEventCreateWithFlags(&ev_join, cudaEventDisableTiming);
    }

    // Fork: tensor-core GEMM overlaps the edge-prep chain.
    cudaEventRecord(ev_fork, 0);
    cudaStreamWaitEvent(s_side, ev_fork, 0);
    k_gemm<<<(NN + 127) / 128, 256, 0, s_side>>>(x, W);
    cudaEventRecord(ev_join, s_side);

    k_detect<<<1, 1024>>>(ei);
    k_zero<<<(NN + 255) / 256, 256>>>();
    k_degree<<<(EE + 255) / 256, 256>>>(ei);
    k_scan1<<<SCAN_BLOCKS, 1024>>>();
    k_scan2<<<1, 32>>>(SCAN_BLOCKS);
    k_scan3<<<(NN + 255) / 256, 256>>>();
    k_fill<<<(EE + 255) / 256, 256>>>(ei);

    cudaStreamWaitEvent(0, ev_join, 0);
    k_gather<<<(NN + 7) / 8, 256>>>(b);
    k_bnparam<<<1, 128>>>(gamma, beta);
    k_final<<<(NN * 32 + 255) / 256, 256>>>(x, out);
}

// round 10
// speedup vs baseline: 1.7041x; 1.1137x over previous
#include <cuda_runtime.h>

#define NN 100000
#define EE 600000
#define DD 128
#define SCAN_BLOCKS 98   // ceil(100000/1024)

typedef unsigned long long u64;

// ---------------- scratch (static __device__, no allocation) ----------------
__device__ float g_h[(size_t)NN * DD];     // x @ W
__device__ float g_acc[(size_t)NN * DD];   // aggregated messages
__device__ float g_dinv[NN];
__device__ int   g_deg[NN];
__device__ int   g_rowstart[NN];
__device__ int   g_pos[NN];
__device__ int   g_bsum[128];
__device__ int   g_flag[128];
__device__ int   g_ticket;
__device__ int2  g_emeta[EE];              // {src, bitcast(norm)}
__device__ float g_colsum[DD];
__device__ float g_colsumsq[DD];
__device__ float g_scale[DD];
__device__ float g_shift[DD];
__device__ int   g_ei32;                   // 1 if edge_index stored as int32

// ---------------- edge index decode ----------------
__device__ __forceinline__ int load_src(const void* ei, int e) {
    return g_ei32 ? ((const int*)ei)[e] : (int)((const long long*)ei)[e];
}
__device__ __forceinline__ int load_dst(const void* ei, int e) {
    return g_ei32 ? ((const int*)ei)[EE + e] : (int)((const long long*)ei)[EE + e];
}

// ---------------- prep: zero scratch + dtype sniff (block 0) --------------
__global__ void k_prep(const void* ei) {
    int i = blockIdx.x * blockDim.x + threadIdx.x;
    if (i < NN) g_deg[i] = 0;
    if (i < DD) { g_colsum[i] = 0.f; g_colsumsq[i] = 0.f; }
    if (i < 128) g_flag[i] = 0;
    if (i == 0) g_ticket = 0;
    if (blockIdx.x == 0) {
        // 256 threads x 4 entries = first 1024 int64-decoded values
        const long long* p = (const long long*)ei;
        int t = threadIdx.x;
        int bad = 0;
#pragma unroll
        for (int j = 0; j < 4; j++) {
            long long v = p[t * 4 + j];
            if (v < 0 || v >= NN) bad = 1;
        }
        unsigned m = __ballot_sync(0xFFFFFFFFu, bad);
        __shared__ int s_bad;
        if (t == 0) s_bad = 0;
        __syncthreads();
        if (m && (t & 31) == 0) atomicOr(&s_bad, 1);
        __syncthreads();
        if (t == 0) g_ei32 = s_bad;
    }
}

__global__ void k_degree(const void* __restrict__ ei) {
    int i = blockIdx.x * blockDim.x + threadIdx.x;
    if (i < EE) {
        int d = load_dst(ei, i);
        if ((unsigned)d < NN) atomicAdd(&g_deg[d], 1);
    }
}

// ---------------- fused scan: deg -> rowstart/pos/dinv in ONE kernel ------
// 98 blocks x 1024. Each block publishes its total, then all blocks wait for
// all 98 totals (parallel publish; no chained lookback) and offset locally.
__global__ void k_scanF() {
    __shared__ int s_warp[32];
    __shared__ int s_bsum[SCAN_BLOCKS];
    __shared__ int s_off;
    int t = threadIdx.x;
    int lane = t & 31;
    int wid = t >> 5;
    int blk = blockIdx.x;
    int i = blk * 1024 + t;
    int v = (i < NN) ? g_deg[i] : 0;
    // warp-inclusive scan
    int sc = v;
#pragma unroll
    for (int off = 1; off < 32; off <<= 1) {
        int n = __shfl_up_sync(0xFFFFFFFFu, sc, off);
        if (lane >= off) sc += n;
    }
    if (lane == 31) s_warp[wid] = sc;
    __syncthreads();
    if (wid == 0) {
        int ws = s_warp[lane];
#pragma unroll
        for (int off = 1; off < 32; off <<= 1) {
            int n = __shfl_up_sync(0xFFFFFFFFu, ws, off);
            if (lane >= off) ws += n;
        }
        s_warp[lane] = ws;
    }
    __syncthreads();
    int base = (wid > 0) ? s_warp[wid - 1] : 0;
    // publish block total
    if (t == 1023) {
        g_bsum[blk] = base + sc;
        __threadfence();
        atomicExch(&g_flag[blk], 1);
    }
    // wait for ALL block totals (producers never depend on waiters: no deadlock)
    if (t < SCAN_BLOCKS) {
        while (atomicAdd(&g_flag[t], 0) == 0) { }
        s_bsum[t] = g_bsum[t];
    }
    __syncthreads();
    if (t == 0) {
        int r = 0;
        for (int j = 0; j < blk; j++) r += s_bsum[j];
        s_off = r;
    }
    __syncthreads();
    if (i < NN) {
        int rs = s_off + base + sc - v;
        g_rowstart[i] = rs;
        g_pos[i] = rs;
        g_dinv[i] = rsqrtf((float)g_deg[i] + 1.0f);
    }
}

__global__ void k_fill(const void* __restrict__ ei) {
    int e = blockIdx.x * blockDim.x + threadIdx.x;
    if (e >= EE) return;
    int src = load_src(ei, e);
    int dst = load_dst(ei, e);
    if ((unsigned)src >= NN || (unsigned)dst >= NN) return;
    float nrm = g_dinv[src] * g_dinv[dst];
    int slot = atomicAdd(&g_pos[dst], 1);
    g_emeta[slot] = make_int2(src, __float_as_int(nrm));
}

// ---------------- GEMM: h = X @ W via mma.sync tf32 tensor cores ----------
__device__ __forceinline__ unsigned tf32cvt(float f) {
    unsigned r; asm("cvt.rna.tf32.f32 %0, %1;" : "=r"(r) : "f"(f)); return r;
}

__global__ void __launch_bounds__(256, 2)
k_gemm(const float* __restrict__ X, const float* __restrict__ W) {
    __shared__ unsigned Xs[128 * 36];   // [row][k] stride 36
    __shared__ unsigned Ws[32 * 136];   // [k][n]  stride 136
    const int tid  = threadIdx.x;
    const int lane = tid & 31;
    const int warp = tid >> 5;
    const int g    = lane >> 2;
    const int t4   = lane & 3;
    const int wm   = (warp & 1) * 64;
    const int wn   = (warp >> 1) * 32;
    const int rowBase = blockIdx.x * 128;

    float acc[4][4][4];
#pragma unroll
    for (int i = 0; i < 4; i++)
#pragma unroll
        for (int j = 0; j < 4; j++)
#pragma unroll
            for (int c = 0; c < 4; c++) acc[i][j][c] = 0.f;

    for (int kc = 0; kc < 4; kc++) {
        __syncthreads();
#pragma unroll
        for (int i = 0; i < 16; i++) {
            int idx = tid + 256 * i;
            int kl = idx >> 7;
            int n  = idx & 127;
            Ws[kl * 136 + n] = tf32cvt(W[(size_t)(kc * 32 + kl) * DD + n]);
        }
#pragma unroll
        for (int i = 0; i < 16; i++) {
            int idx = tid + 256 * i;
            int r  = idx >> 5;
            int kl = idx & 31;
            int row = rowBase + r;
            float xv = (row < NN) ? X[(size_t)row * DD + kc * 32 + kl] : 0.f;
            Xs[r * 36 + kl] = tf32cvt(xv);
        }
        __syncthreads();
#pragma unroll
        for (int ks = 0; ks < 4; ks++) {
            const int kb = ks * 8;
            unsigned bf[4][2];
#pragma unroll
            for (int j = 0; j < 4; j++) {
                int n = wn + j * 8 + g;
                bf[j][0] = Ws[(kb + t4) * 136 + n];
                bf[j][1] = Ws[(kb + t4 + 4) * 136 + n];
            }
#pragma unroll
            for (int i = 0; i < 4; i++) {
                int r0 = wm + i * 16 + g;
                unsigned a0 = Xs[r0 * 36 + kb + t4];
                unsigned a1 = Xs[(r0 + 8) * 36 + kb + t4];
                unsigned a2 = Xs[r0 * 36 + kb + t4 + 4];
                unsigned a3 = Xs[(r0 + 8) * 36 + kb + t4 + 4];
#pragma unroll
                for (int j = 0; j < 4; j++) {
                    asm volatile(
                        "mma.sync.aligned.m16n8k8.row.col.f32.tf32.tf32.f32 "
                        "{%0,%1,%2,%3}, {%4,%5,%6,%7}, {%8,%9}, {%0,%1,%2,%3};"
                        : "+f"(acc[i][j][0]), "+f"(acc[i][j][1]),
                          "+f"(acc[i][j][2]), "+f"(acc[i][j][3])
                        : "r"(a0), "r"(a1), "r"(a2), "r"(a3),
                          "r"(bf[j][0]), "r"(bf[j][1]));
                }
            }
        }
    }
#pragma unroll
    for (int i = 0; i < 4; i++) {
        int rbase = rowBase + wm + i * 16 + g;
#pragma unroll
        for (int half = 0; half < 2; half++) {
            int r = rbase + half * 8;
            if (r < NN) {
                float2* p = (float2*)(g_h + (size_t)r * DD + wn);
#pragma unroll
                for (int j = 0; j < 4; j++)
                    p[j * 4 + t4] = make_float2(acc[i][j][half * 2],
                                                acc[i][j][half * 2 + 1]);
            }
        }
    }
}

// ---------------- gather: warp/node, 4-edge pipeline, fused BN stats ------
// 512 threads = 16 nodes per block. Last block computes scale/shift.
__global__ void k_gather(const float* __restrict__ b,
                         const float* __restrict__ gamma,
                         const float* __restrict__ beta) {
    __shared__ float s_sum[DD];
    __shared__ float s_sumsq[DD];
    __shared__ int s_last;
    int t = threadIdx.x;
    if (t < DD) { s_sum[t] = 0.f; s_sumsq[t] = 0.f; }
    __syncthreads();

    int lane = t & 31;
    int node = blockIdx.x * 16 + (t >> 5);
    if (node < NN) {
        float dv = g_dinv[node];
        float4 hv = ((const float4*)(g_h + (size_t)node * DD))[lane];
        float4 bb = ((const float4*)b)[lane];
        float nrm0 = dv * dv;
        float4 a = make_float4(hv.x * nrm0 + bb.x, hv.y * nrm0 + bb.y,
                               hv.z * nrm0 + bb.z, hv.w * nrm0 + bb.w);
        int e   = g_rowstart[node];
        int end = e + g_deg[node];
        for (; e + 3 < end; e += 4) {
            int2 m0 = g_emeta[e];
            int2 m1 = g_emeta[e + 1];
            int2 m2 = g_emeta[e + 2];
            int2 m3 = g_emeta[e + 3];
            float4 v0 = ((const float4*)(g_h + (size_t)m0.x * DD))[lane];
            float4 v1 = ((const float4*)(g_h + (size_t)m1.x * DD))[lane];
            float4 v2 = ((const float4*)(g_h + (size_t)m2.x * DD))[lane];
            float4 v3 = ((const float4*)(g_h + (size_t)m3.x * DD))[lane];
            float n0 = __int_as_float(m0.y), n1 = __int_as_float(m1.y);
            float n2 = __int_as_float(m2.y), n3 = __int_as_float(m3.y);
            a.x += v0.x * n0; a.y += v0.y * n0; a.z += v0.z * n0; a.w += v0.w * n0;
            a.x += v1.x * n1; a.y += v1.y * n1; a.z += v1.z * n1; a.w += v1.w * n1;
            a.x += v2.x * n2; a.y += v2.y * n2; a.z += v2.z * n2; a.w += v2.w * n2;
            a.x += v3.x * n3; a.y += v3.y * n3; a.z += v3.z * n3; a.w += v3.w * n3;
        }
        for (; e < end; e++) {
            int2 m = g_emeta[e];
            float nrm = __int_as_float(m.y);
            float4 v = ((const float4*)(g_h + (size_t)m.x * DD))[lane];
            a.x += v.x * nrm; a.y += v.y * nrm;
            a.z += v.z * nrm; a.w += v.w * nrm;
        }
        ((float4*)(g_acc + (size_t)node * DD))[lane] = a;
        int c = lane * 4;
        atomicAdd(&s_sum[c + 0], a.x); atomicAdd(&s_sumsq[c + 0], a.x * a.x);
        atomicAdd(&s_sum[c + 1], a.y); atomicAdd(&s_sumsq[c + 1], a.y * a.y);
        atomicAdd(&s_sum[c + 2], a.z); atomicAdd(&s_sumsq[c + 2], a.z * a.z);
        atomicAdd(&s_sum[c + 3], a.w); atomicAdd(&s_sumsq[c + 3], a.w * a.w);
    }
    __syncthreads();
    if (t < DD)            atomicAdd(&g_colsum[t], s_sum[t]);
    else if (t < 2 * DD)   atomicAdd(&g_colsumsq[t - DD], s_sumsq[t - DD]);

    // last-block computes BN scale/shift
    __threadfence();
    __syncthreads();
    if (t == 0) s_last = (atomicAdd(&g_ticket, 1) == (int)gridDim.x - 1);
    __syncthreads();
    if (s_last && t < DD) {
        float mean = g_colsum[t] * (1.0f / (float)NN);
        float var  = g_colsumsq[t] * (1.0f / (float)NN) - mean * mean;
        float rstd = rsqrtf(var + 1e-5f);
        float sc   = rstd * gamma[t];
        g_scale[t] = sc;
        g_shift[t] = beta[t] - mean * sc;
    }
}

// out = relu(acc*scale + shift) + x
__global__ void k_final(const float* __restrict__ X, float* __restrict__ out) {
    int idx = blockIdx.x * blockDim.x + threadIdx.x;
    if (idx >= NN * 32) return;
    int c4 = idx & 31;
    float4 a  = ((const float4*)g_acc)[idx];
    float4 sc = ((const float4*)g_scale)[c4];
    float4 sh = ((const float4*)g_shift)[c4];
    float4 xv = ((const float4*)X)[idx];
    float4 o;
    o.x = fmaxf(a.x * sc.x + sh.x, 0.f) + xv.x;
    o.y = fmaxf(a.y * sc.y + sh.y, 0.f) + xv.y;
    o.z = fmaxf(a.z * sc.z + sh.z, 0.f) + xv.z;
    o.w = fmaxf(a.w * sc.w + sh.w, 0.f) + xv.w;
    ((float4*)out)[idx] = o;
}

// ---------------- launch ----------------
extern "C" void kernel_launch(void* const* d_in, const int* in_sizes, int n_in,
                              void* d_out, int out_size) {
    const float* x = nullptr; const void* ei = nullptr; const float* W = nullptr;
    const float* b = nullptr; const float* gamma = nullptr; const float* beta = nullptr;
    for (int i = 0; i < n_in; i++) {
        int sz = in_sizes[i];
        if (sz == NN * DD)      x  = (const float*)d_in[i];
        else if (sz == 2 * EE)  ei = d_in[i];
        else if (sz == DD * DD) W  = (const float*)d_in[i];
        else if (sz == DD) {
            if (!b) b = (const float*)d_in[i];
            else if (!gamma) gamma = (const float*)d_in[i];
            else beta = (const float*)d_in[i];
        }
    }
    float* out = (float*)d_out;

    static cudaStream_t s_side = nullptr;
    static cudaEvent_t ev_fork = nullptr, ev_join = nullptr;
    if (!s_side) {
        cudaStreamCreateWithFlags(&s_side, cudaStreamNonBlocking);
        cudaEventCreateWithFlags(&ev_fork, cudaEventDisableTiming);
        cudaEventCreateWithFlags(&ev_join, cudaEventDisableTiming);
    }

    // Fork: tensor-core GEMM overlaps the edge-prep chain.
    cudaEventRecord(ev_fork, 0);
    cudaStreamWaitEvent(s_side, ev_fork, 0);
    k_gemm<<<(NN + 127) / 128, 256, 0, s_side>>>(x, W);
    cudaEventRecord(ev_join, s_side);

    // Edge-prep chain (4 launches).
    k_prep<<<(NN + 255) / 256, 256>>>(ei);
    k_degree<<<(EE + 255) / 256, 256>>>(ei);
    k_scanF<<<SCAN_BLOCKS, 1024>>>();
    k_fill<<<(EE + 255) / 256, 256>>>(ei);

    // Join, then gather (with fused BN-param tail) and final.
    cudaStreamWaitEvent(0, ev_join, 0);
    k_gather<<<(NN + 15) / 16, 512>>>(b, gamma, beta);
    k_final<<<(NN * 32 + 255) / 256, 256>>>(x, out);
}

// round 11
// speedup vs baseline: 1.7947x; 1.0532x over previous
#include <cuda_runtime.h>

#define NN 100000
#define EE 600000
#define DD 128
#define SCAN_BLOCKS 98   // ceil(100000/1024)

typedef unsigned long long u64;

// ---------------- scratch (static __device__, no allocation) ----------------
__device__ float g_h[(size_t)NN * DD];     // x @ W
__device__ float g_acc[(size_t)NN * DD];   // aggregated messages
__device__ float g_dinv[NN];
__device__ int   g_deg[NN];
__device__ int   g_rowstart[NN];
__device__ int   g_pos[NN];
__device__ int   g_bsum[128];
__device__ int   g_flag[128];
__device__ int   g_ticket;
__device__ int2  g_emeta[EE];              // {src, bitcast(norm)}
__device__ float g_colsum[DD];
__device__ float g_colsumsq[DD];
__device__ float g_scale[DD];
__device__ float g_shift[DD];
__device__ int   g_ei32;                   // 1 if edge_index stored as int32

// ---------------- edge index decode (32-bit low-word path) ----------------
// Values are guarded by (unsigned)<NN and the dtype sniff, so reading the
// low 32 bits of an int64 entry is sufficient and halves index traffic.
__device__ __forceinline__ int load_src(const void* ei, int e) {
    return g_ei32 ? ((const int*)ei)[e] : ((const int*)ei)[2 * e];
}
__device__ __forceinline__ int load_dst(const void* ei, int e) {
    return g_ei32 ? ((const int*)ei)[EE + e] : ((const int*)ei)[2 * (EE + e)];
}

// ---------------- prep: zero scratch + dtype sniff (block 0) --------------
__global__ void k_prep(const void* ei) {
    int i = blockIdx.x * blockDim.x + threadIdx.x;
    if (i < NN) g_deg[i] = 0;
    if (i < DD) { g_colsum[i] = 0.f; g_colsumsq[i] = 0.f; }
    if (i < 128) g_flag[i] = 0;
    if (i == 0) g_ticket = 0;
    if (blockIdx.x == 0) {
        const long long* p = (const long long*)ei;
        int t = threadIdx.x;
        int bad = 0;
#pragma unroll
        for (int j = 0; j < 4; j++) {
            long long v = p[t * 4 + j];
            if (v < 0 || v >= NN) bad = 1;
        }
        unsigned m = __ballot_sync(0xFFFFFFFFu, bad);
        __shared__ int s_bad;
        if (t == 0) s_bad = 0;
        __syncthreads();
        if (m && (t & 31) == 0) atomicOr(&s_bad, 1);
        __syncthreads();
        if (t == 0) g_ei32 = s_bad;
    }
}

__global__ void k_degree(const void* __restrict__ ei) {
    int i = blockIdx.x * blockDim.x + threadIdx.x;
    if (i < EE) {
        int d = load_dst(ei, i);
        if ((unsigned)d < NN) atomicAdd(&g_deg[d], 1);
    }
}

// ---------------- fused scan: deg -> rowstart/pos/dinv in ONE kernel ------
__global__ void k_scanF() {
    __shared__ int s_warp[32];
    __shared__ int s_bsum[SCAN_BLOCKS];
    __shared__ int s_off;
    int t = threadIdx.x;
    int lane = t & 31;
    int wid = t >> 5;
    int blk = blockIdx.x;
    int i = blk * 1024 + t;
    int v = (i < NN) ? g_deg[i] : 0;
    int sc = v;
#pragma unroll
    for (int off = 1; off < 32; off <<= 1) {
        int n = __shfl_up_sync(0xFFFFFFFFu, sc, off);
        if (lane >= off) sc += n;
    }
    if (lane == 31) s_warp[wid] = sc;
    __syncthreads();
    if (wid == 0) {
        int ws = s_warp[lane];
#pragma unroll
        for (int off = 1; off < 32; off <<= 1) {
            int n = __shfl_up_sync(0xFFFFFFFFu, ws, off);
            if (lane >= off) ws += n;
        }
        s_warp[lane] = ws;
    }
    __syncthreads();
    int base = (wid > 0) ? s_warp[wid - 1] : 0;
    if (t == 1023) {
        g_bsum[blk] = base + sc;
        __threadfence();
        atomicExch(&g_flag[blk], 1);
    }
    if (t < SCAN_BLOCKS) {
        while (atomicAdd(&g_flag[t], 0) == 0) { }
        s_bsum[t] = g_bsum[t];
    }
    __syncthreads();
    if (t == 0) {
        int r = 0;
        for (int j = 0; j < blk; j++) r += s_bsum[j];
        s_off = r;
    }
    __syncthreads();
    if (i < NN) {
        int rs = s_off + base + sc - v;
        g_rowstart[i] = rs;
        g_pos[i] = rs;
        g_dinv[i] = rsqrtf((float)g_deg[i] + 1.0f);
    }
}

__global__ void k_fill(const void* __restrict__ ei) {
    int e = blockIdx.x * blockDim.x + threadIdx.x;
    if (e >= EE) return;
    int src = load_src(ei, e);
    int dst = load_dst(ei, e);
    if ((unsigned)src >= NN || (unsigned)dst >= NN) return;
    float nrm = g_dinv[src] * g_dinv[dst];
    int slot = atomicAdd(&g_pos[dst], 1);
    g_emeta[slot] = make_int2(src, __float_as_int(nrm));
}

// ---------------- GEMM: tf32 mma.sync, DOUBLE-BUFFERED staging ------------
// Block: 128 rows x 128 cols, 8 K-chunks of 16, two smem buffers.
// While chunk c is consumed by MMAs, chunk c+1's global loads land in buf^1.
__device__ __forceinline__ unsigned tf32cvt(float f) {
    unsigned r; asm("cvt.rna.tf32.f32 %0, %1;" : "=r"(r) : "f"(f)); return r;
}

#define XS_STRIDE 20   // [row][k] k=16 +4 pad: A-frag bank-conflict-free
#define WS_STRIDE 136  // [k][n] 128 +8 pad: B-frag bank-conflict-free

__global__ void __launch_bounds__(256, 2)
k_gemm(const float* __restrict__ X, const float* __restrict__ W) {
    __shared__ unsigned Xs[2][128 * XS_STRIDE];
    __shared__ unsigned Ws[2][16 * WS_STRIDE];
    const int tid  = threadIdx.x;
    const int lane = tid & 31;
    const int warp = tid >> 5;
    const int g    = lane >> 2;
    const int t4   = lane & 3;
    const int wm   = (warp & 1) * 64;
    const int wn   = (warp >> 1) * 32;
    const int rowBase = blockIdx.x * 128;

    float acc[4][4][4];
#pragma unroll
    for (int i = 0; i < 4; i++)
#pragma unroll
        for (int j = 0; j < 4; j++)
#pragma unroll
            for (int c = 0; c < 4; c++) acc[i][j][c] = 0.f;

    // stage chunk kc into buffer bb (W: 16x128 = 2048 elts; X: 128x16 = 2048)
    auto stage = [&](int kc, int bb) {
#pragma unroll
        for (int i = 0; i < 8; i++) {
            int idx = tid + 256 * i;
            int kl = idx >> 7;          // 0..15
            int n  = idx & 127;
            Ws[bb][kl * WS_STRIDE + n] = tf32cvt(W[(size_t)(kc * 16 + kl) * DD + n]);
        }
#pragma unroll
        for (int i = 0; i < 8; i++) {
            int idx = tid + 256 * i;
            int r  = idx >> 4;          // 0..127
            int kl = idx & 15;
            int row = rowBase + r;
            float xv = (row < NN) ? X[(size_t)row * DD + kc * 16 + kl] : 0.f;
            Xs[bb][r * XS_STRIDE + kl] = tf32cvt(xv);
        }
    };

    stage(0, 0);
    __syncthreads();

    for (int kc = 0; kc < 8; kc++) {
        int bb = kc & 1;
        if (kc + 1 < 8) stage(kc + 1, bb ^ 1);   // loads overlap MMAs below
#pragma unroll
        for (int ks = 0; ks < 2; ks++) {
            const int kb = ks * 8;
            unsigned bf[4][2];
#pragma unroll
            for (int j = 0; j < 4; j++) {
                int n = wn + j * 8 + g;
                bf[j][0] = Ws[bb][(kb + t4) * WS_STRIDE + n];
                bf[j][1] = Ws[bb][(kb + t4 + 4) * WS_STRIDE + n];
            }
#pragma unroll
            for (int i = 0; i < 4; i++) {
                int r0 = wm + i * 16 + g;
                unsigned a0 = Xs[bb][r0 * XS_STRIDE + kb + t4];
                unsigned a1 = Xs[bb][(r0 + 8) * XS_STRIDE + kb + t4];
                unsigned a2 = Xs[bb][r0 * XS_STRIDE + kb + t4 + 4];
                unsigned a3 = Xs[bb][(r0 + 8) * XS_STRIDE + kb + t4 + 4];
#pragma unroll
                for (int j = 0; j < 4; j++) {
                    asm volatile(
                        "mma.sync.aligned.m16n8k8.row.col.f32.tf32.tf32.f32 "
                        "{%0,%1,%2,%3}, {%4,%5,%6,%7}, {%8,%9}, {%0,%1,%2,%3};"
                        : "+f"(acc[i][j][0]), "+f"(acc[i][j][1]),
                          "+f"(acc[i][j][2]), "+f"(acc[i][j][3])
                        : "r"(a0), "r"(a1), "r"(a2), "r"(a3),
                          "r"(bf[j][0]), "r"(bf[j][1]));
                }
            }
        }
        __syncthreads();   // next buffer fully staged; this buffer free
    }

#pragma unroll
    for (int i = 0; i < 4; i++) {
        int rbase = rowBase + wm + i * 16 + g;
#pragma unroll
        for (int half = 0; half < 2; half++) {
            int r = rbase + half * 8;
            if (r < NN) {
                float2* p = (float2*)(g_h + (size_t)r * DD + wn);
#pragma unroll
                for (int j = 0; j < 4; j++)
                    p[j * 4 + t4] = make_float2(acc[i][j][half * 2],
                                                acc[i][j][half * 2 + 1]);
            }
        }
    }
}

// ---------------- gather: warp/node, prefetched 4-edge pipeline -----------
__global__ void k_gather(const float* __restrict__ b,
                         const float* __restrict__ gamma,
                         const float* __restrict__ beta) {
    __shared__ float s_sum[DD];
    __shared__ float s_sumsq[DD];
    __shared__ int s_last;
    int t = threadIdx.x;
    if (t < DD) { s_sum[t] = 0.f; s_sumsq[t] = 0.f; }
    __syncthreads();

    int lane = t & 31;
    int node = blockIdx.x * 16 + (t >> 5);
    if (node < NN) {
        float dv = g_dinv[node];
        float4 hv = __ldg(&((const float4*)(g_h + (size_t)node * DD))[lane]);
        float4 bb = __ldg(&((const float4*)b)[lane]);
        float nrm0 = dv * dv;
        float4 a = make_float4(hv.x * nrm0 + bb.x, hv.y * nrm0 + bb.y,
                               hv.z * nrm0 + bb.z, hv.w * nrm0 + bb.w);
        int e   = g_rowstart[node];
        int end = e + g_deg[node];
        if (e + 3 < end) {
            // prefetch first meta group
            int2 m0 = __ldg(&g_emeta[e]),     m1 = __ldg(&g_emeta[e + 1]);
            int2 m2 = __ldg(&g_emeta[e + 2]), m3 = __ldg(&g_emeta[e + 3]);
            for (;;) {
                int en = e + 4;
                bool more = (en + 3 < end);
                int2 p0, p1, p2, p3;
                if (more) {        // next group's meta loads overlap h loads
                    p0 = __ldg(&g_emeta[en]);     p1 = __ldg(&g_emeta[en + 1]);
                    p2 = __ldg(&g_emeta[en + 2]); p3 = __ldg(&g_emeta[en + 3]);
                }
                float4 v0 = __ldg(&((const float4*)(g_h + (size_t)m0.x * DD))[lane]);
                float4 v1 = __ldg(&((const float4*)(g_h + (size_t)m1.x * DD))[lane]);
                float4 v2 = __ldg(&((const float4*)(g_h + (size_t)m2.x * DD))[lane]);
                float4 v3 = __ldg(&((const float4*)(g_h + (size_t)m3.x * DD))[lane]);
                float n0 = __int_as_float(m0.y), n1 = __int_as_float(m1.y);
                float n2 = __int_as_float(m2.y), n3 = __int_as_float(m3.y);
                a.x += v0.x * n0; a.y += v0.y * n0; a.z += v0.z * n0; a.w += v0.w * n0;
                a.x += v1.x * n1; a.y += v1.y * n1; a.z += v1.z * n1; a.w += v1.w * n1;
                a.x += v2.x * n2; a.y += v2.y * n2; a.z += v2.z * n2; a.w += v2.w * n2;
                a.x += v3.x * n3; a.y += v3.y * n3; a.z += v3.z * n3; a.w += v3.w * n3;
                e = en;
                if (!more) break;
                m0 = p0; m1 = p1; m2 = p2; m3 = p3;
            }
        }
        for (; e < end; e++) {
            int2 m = __ldg(&g_emeta[e]);
            float nrm = __int_as_float(m.y);
            float4 v = __ldg(&((const float4*)(g_h + (size_t)m.x * DD))[lane]);
            a.x += v.x * nrm; a.y += v.y * nrm;
            a.z += v.z * nrm; a.w += v.w * nrm;
        }
        ((float4*)(g_acc + (size_t)node * DD))[lane] = a;
        int c = lane * 4;
        atomicAdd(&s_sum[c + 0], a.x); atomicAdd(&s_sumsq[c + 0], a.x * a.x);
        atomicAdd(&s_sum[c + 1], a.y); atomicAdd(&s_sumsq[c + 1], a.y * a.y);
        atomicAdd(&s_sum[c + 2], a.z); atomicAdd(&s_sumsq[c + 2], a.z * a.z);
        atomicAdd(&s_sum[c + 3], a.w); atomicAdd(&s_sumsq[c + 3], a.w * a.w);
    }
    __syncthreads();
    if (t < DD)            atomicAdd(&g_colsum[t], s_sum[t]);
    else if (t < 2 * DD)   atomicAdd(&g_colsumsq[t - DD], s_sumsq[t - DD]);

    __threadfence();
    __syncthreads();
    if (t == 0) s_last = (atomicAdd(&g_ticket, 1) == (int)gridDim.x - 1);
    __syncthreads();
    if (s_last && t < DD) {
        float mean = g_colsum[t] * (1.0f / (float)NN);
        float var  = g_colsumsq[t] * (1.0f / (float)NN) - mean * mean;
        float rstd = rsqrtf(var + 1e-5f);
        float sc   = rstd * gamma[t];
        g_scale[t] = sc;
        g_shift[t] = beta[t] - mean * sc;
    }
}

// out = relu(acc*scale + shift) + x
__global__ void k_final(const float* __restrict__ X, float* __restrict__ out) {
    int idx = blockIdx.x * blockDim.x + threadIdx.x;
    if (idx >= NN * 32) return;
    int c4 = idx & 31;
    float4 a  = ((const float4*)g_acc)[idx];
    float4 sc = ((const float4*)g_scale)[c4];
    float4 sh = ((const float4*)g_shift)[c4];
    float4 xv = ((const float4*)X)[idx];
    float4 o;
    o.x = fmaxf(a.x * sc.x + sh.x, 0.f) + xv.x;
    o.y = fmaxf(a.y * sc.y + sh.y, 0.f) + xv.y;
    o.z = fmaxf(a.z * sc.z + sh.z, 0.f) + xv.z;
    o.w = fmaxf(a.w * sc.w + sh.w, 0.f) + xv.w;
    ((float4*)out)[idx] = o;
}

// ---------------- launch ----------------
extern "C" void kernel_launch(void* const* d_in, const int* in_sizes, int n_in,
                              void* d_out, int out_size) {
    const float* x = nullptr; const void* ei = nullptr; const float* W = nullptr;
    const float* b = nullptr; const float* gamma = nullptr; const float* beta = nullptr;
    for (int i = 0; i < n_in; i++) {
        int sz = in_sizes[i];
        if (sz == NN * DD)      x  = (const float*)d_in[i];
        else if (sz == 2 * EE)  ei = d_in[i];
        else if (sz == DD * DD) W  = (const float*)d_in[i];
        else if (sz == DD) {
            if (!b) b = (const float*)d_in[i];
            else if (!gamma) gamma = (const float*)d_in[i];
            else beta = (const float*)d_in[i];
        }
    }
    float* out = (float*)d_out;

    static cudaStream_t s_side = nullptr;
    static cudaEvent_t ev_fork = nullptr, ev_join = nullptr;
    if (!s_side) {
        cudaStreamCreateWithFlags(&s_side, cudaStreamNonBlocking);
        cudaEventCreateWithFlags(&ev_fork, cudaEventDisableTiming);
        cudaEventCreateWithFlags(&ev_join, cudaEventDisableTiming);
    }

    // Fork: tensor-core GEMM overlaps the edge-prep chain.
    cudaEventRecord(ev_fork, 0);
    cudaStreamWaitEvent(s_side, ev_fork, 0);
    k_gemm<<<(NN + 127) / 128, 256, 0, s_side>>>(x, W);
    cudaEventRecord(ev_join, s_side);

    // Edge-prep chain.
    k_prep<<<(NN + 255) / 256, 256>>>(ei);
    k_degree<<<(EE + 255) / 256, 256>>>(ei);
    k_scanF<<<SCAN_BLOCKS, 1024>>>();
    k_fill<<<(EE + 255) / 256, 256>>>(ei);

    // Join, then gather (with fused BN-param tail) and final.
    cudaStreamWaitEvent(0, ev_join, 0);
    k_gather<<<(NN + 15) / 16, 512>>>(b, gamma, beta);
    k_final<<<(NN * 32 + 255) / 256, 256>>>(x, out);
}